// round 1
// baseline (speedup 1.0000x reference)
#include <cuda_runtime.h>

// Problem shapes (fixed for this instance):
//   B=4, T=2048, C=2048, nH=16, hd=128
//   x    [B,T,C]      f32
//   Wqkv [3C, C]      f32
//   bqkv [3C]         f32
//   Wout [C, C]       f32
//   bout [C]          f32
// Output = concat(y [B,T,C], new_k [B,nH,T,hd], new_v [B,nH,T,hd])

#define C_DIM   2048
#define T_DIM   2048
#define B_DIM   4
#define NH      16
#define HD      128
#define MTOT    (B_DIM * T_DIM)         // 8192
#define YELEMS  (B_DIM * T_DIM * C_DIM) // 16777216

// Scratch (allocation-free rule: __device__ globals)
__device__ float g_qbuf[YELEMS];   // q in [B,nH,T,hd]
__device__ float g_ybuf[YELEMS];   // attention output in [B,T,C]

// ---------------------------------------------------------------------------
// SGEMM: C[m,n] = sum_k A[m,k] * W[n,k]  (+ bias), 128x128 block, 8x8/thread
// ---------------------------------------------------------------------------
#define GBM 128
#define GBN 128
#define GBK 16

// MODE 0: QKV projection. Scatter into q scratch / k out / v out in
//         [B,nH,T,hd] layout. N tile (128 cols) never straddles a head or
//         a q/k/v segment boundary, so seg and h are per-block constants.
// MODE 1: output projection, plain row-major [M, 2048] store.
template <int MODE>
__global__ __launch_bounds__(256) void gemm_nt_kernel(
    const float* __restrict__ A,      // [M, 2048]
    const float* __restrict__ W,      // [N, 2048]
    const float* __restrict__ bias,   // [N]
    float* __restrict__ out0,         // MODE0: k out ; MODE1: y out
    float* __restrict__ out1)         // MODE0: v out ; MODE1: unused
{
    const int K = C_DIM;
    __shared__ float As[GBK][GBM];
    __shared__ float Bs[GBK][GBN];

    const int tid = threadIdx.x;
    const int tx = tid & 15;
    const int ty = tid >> 4;
    const int m0 = blockIdx.y * GBM;
    const int n0 = blockIdx.x * GBN;

    float acc[8][8];
#pragma unroll
    for (int i = 0; i < 8; i++)
#pragma unroll
        for (int j = 0; j < 8; j++) acc[i][j] = 0.0f;

    for (int k0 = 0; k0 < K; k0 += GBK) {
#pragma unroll
        for (int r = 0; r < 2; r++) {
            int idx = tid + r * 256;        // 0..511
            int row = idx >> 2;             // 0..127
            int kq  = (idx & 3) << 2;       // 0,4,8,12
            const float4 va = *reinterpret_cast<const float4*>(
                &A[(m0 + row) * K + k0 + kq]);
            As[kq + 0][row] = va.x; As[kq + 1][row] = va.y;
            As[kq + 2][row] = va.z; As[kq + 3][row] = va.w;
            const float4 vb = *reinterpret_cast<const float4*>(
                &W[(n0 + row) * K + k0 + kq]);
            Bs[kq + 0][row] = vb.x; Bs[kq + 1][row] = vb.y;
            Bs[kq + 2][row] = vb.z; Bs[kq + 3][row] = vb.w;
        }
        __syncthreads();
#pragma unroll
        for (int kk = 0; kk < GBK; kk++) {
            float a[8], b[8];
            *reinterpret_cast<float4*>(&a[0]) =
                *reinterpret_cast<float4*>(&As[kk][ty * 8]);
            *reinterpret_cast<float4*>(&a[4]) =
                *reinterpret_cast<float4*>(&As[kk][ty * 8 + 4]);
            *reinterpret_cast<float4*>(&b[0]) =
                *reinterpret_cast<float4*>(&Bs[kk][tx * 8]);
            *reinterpret_cast<float4*>(&b[4]) =
                *reinterpret_cast<float4*>(&Bs[kk][tx * 8 + 4]);
#pragma unroll
            for (int i = 0; i < 8; i++)
#pragma unroll
                for (int j = 0; j < 8; j++) acc[i][j] += a[i] * b[j];
        }
        __syncthreads();
    }

    // bias for this thread's 8 columns
    float bb[8];
#pragma unroll
    for (int j = 0; j < 8; j++) bb[j] = bias[n0 + tx * 8 + j];

    if (MODE == 0) {
        const int seg = n0 >> 11;           // 0=q, 1=k, 2=v
        const int hh  = (n0 & 2047) >> 7;   // head (constant per block)
        float* outp = (seg == 0) ? g_qbuf : ((seg == 1) ? out0 : out1);
#pragma unroll
        for (int i = 0; i < 8; i++) {
            int m = m0 + ty * 8 + i;
            int bb_ = m >> 11;
            int t   = m & 2047;
            float* dst = outp + (((bb_ * NH + hh) * T_DIM) + t) * HD + tx * 8;
            float4 r0, r1;
            r0.x = acc[i][0] + bb[0]; r0.y = acc[i][1] + bb[1];
            r0.z = acc[i][2] + bb[2]; r0.w = acc[i][3] + bb[3];
            r1.x = acc[i][4] + bb[4]; r1.y = acc[i][5] + bb[5];
            r1.z = acc[i][6] + bb[6]; r1.w = acc[i][7] + bb[7];
            *reinterpret_cast<float4*>(&dst[0]) = r0;
            *reinterpret_cast<float4*>(&dst[4]) = r1;
        }
    } else {
#pragma unroll
        for (int i = 0; i < 8; i++) {
            int m = m0 + ty * 8 + i;
            float* dst = out0 + (size_t)m * C_DIM + n0 + tx * 8;
            float4 r0, r1;
            r0.x = acc[i][0] + bb[0]; r0.y = acc[i][1] + bb[1];
            r0.z = acc[i][2] + bb[2]; r0.w = acc[i][3] + bb[3];
            r1.x = acc[i][4] + bb[4]; r1.y = acc[i][5] + bb[5];
            r1.z = acc[i][6] + bb[6]; r1.w = acc[i][7] + bb[7];
            *reinterpret_cast<float4*>(&dst[0]) = r0;
            *reinterpret_cast<float4*>(&dst[4]) = r1;
        }
    }
}

// ---------------------------------------------------------------------------
// Flash attention, causal. One block = one (b,h, 64-row q tile).
// BQ=BK=64, hd=128. Online softmax, O in registers (4 rows x 8 cols / thread).
// P tile reuses the K smem buffer. smem = 3 * 64 * 132 * 4 = 101376 B.
// ---------------------------------------------------------------------------
#define ALD 132  // padded row stride (floats), keeps float4 alignment

__global__ __launch_bounds__(256, 2) void attn_kernel(
    const float* __restrict__ Kt,   // [B,nH,T,hd]
    const float* __restrict__ Vt,   // [B,nH,T,hd]
    int dummy)
{
    extern __shared__ float smem[];
    float* Qs = smem;
    float* Ks = smem + 64 * ALD;
    float* Vs = smem + 2 * 64 * ALD;
    float* Ps = Ks;  // alias: K tile no longer needed once S is in registers

    const int tid = threadIdx.x;
    const int tx = tid & 15;
    const int ty = tid >> 4;
    const int iq = blockIdx.x;     // q tile 0..31
    const int bh = blockIdx.y;     // 0..63
    const int b  = bh >> 4;
    const int h  = bh & 15;

    const float* qp = g_qbuf + ((bh * T_DIM) + iq * 64) * HD;
    const float* kp = Kt + bh * T_DIM * HD;
    const float* vp = Vt + bh * T_DIM * HD;

    // load Q tile (64 x 128)
#pragma unroll
    for (int r = 0; r < 8; r++) {
        int idx = tid + r * 256;     // float4 index, 0..2047
        int row = idx >> 5;          // 32 float4 per row
        int c   = (idx & 31) << 2;
        *reinterpret_cast<float4*>(&Qs[row * ALD + c]) =
            *reinterpret_cast<const float4*>(&qp[row * HD + c]);
    }

    float m_i[4], l_i[4], o[4][8];
#pragma unroll
    for (int r = 0; r < 4; r++) {
        m_i[r] = -1e30f; l_i[r] = 0.0f;
#pragma unroll
        for (int c = 0; c < 8; c++) o[r][c] = 0.0f;
    }

    const float scale = 0.08838834764831843f;  // 1/sqrt(128)

    for (int j = 0; j <= iq; j++) {
        __syncthreads();   // previous-iteration Ps/Vs reads complete
        const float* kb = kp + j * 64 * HD;
        const float* vb = vp + j * 64 * HD;
#pragma unroll
        for (int r = 0; r < 8; r++) {
            int idx = tid + r * 256;
            int row = idx >> 5;
            int c   = (idx & 31) << 2;
            *reinterpret_cast<float4*>(&Ks[row * ALD + c]) =
                *reinterpret_cast<const float4*>(&kb[row * HD + c]);
            *reinterpret_cast<float4*>(&Vs[row * ALD + c]) =
                *reinterpret_cast<const float4*>(&vb[row * HD + c]);
        }
        __syncthreads();

        // S = Q K^T  (4x4 per thread)
        float s[4][4];
#pragma unroll
        for (int r = 0; r < 4; r++)
#pragma unroll
            for (int c = 0; c < 4; c++) s[r][c] = 0.0f;

        for (int d = 0; d < HD; d += 4) {
            float4 qv[4], kv[4];
#pragma unroll
            for (int r = 0; r < 4; r++)
                qv[r] = *reinterpret_cast<float4*>(&Qs[(ty * 4 + r) * ALD + d]);
#pragma unroll
            for (int c = 0; c < 4; c++)
                kv[c] = *reinterpret_cast<float4*>(&Ks[(tx * 4 + c) * ALD + d]);
#pragma unroll
            for (int r = 0; r < 4; r++)
#pragma unroll
                for (int c = 0; c < 4; c++) {
                    s[r][c] += qv[r].x * kv[c].x + qv[r].y * kv[c].y
                             + qv[r].z * kv[c].z + qv[r].w * kv[c].w;
                }
        }

#pragma unroll
        for (int r = 0; r < 4; r++)
#pragma unroll
            for (int c = 0; c < 4; c++) s[r][c] *= scale;

        if (j == iq) {
#pragma unroll
            for (int r = 0; r < 4; r++)
#pragma unroll
                for (int c = 0; c < 4; c++)
                    if (tx * 4 + c > ty * 4 + r) s[r][c] = -1e30f;
        }

        // row max / exp / row sum across the 16-lane tx group
        float mt[4], rs[4], alpha[4];
#pragma unroll
        for (int r = 0; r < 4; r++) {
            float mx = s[r][0];
            mx = fmaxf(mx, s[r][1]); mx = fmaxf(mx, s[r][2]); mx = fmaxf(mx, s[r][3]);
#pragma unroll
            for (int off = 8; off >= 1; off >>= 1)
                mx = fmaxf(mx, __shfl_xor_sync(0xffffffffu, mx, off));
            mt[r] = mx;
        }
#pragma unroll
        for (int r = 0; r < 4; r++) {
            float mnew = fmaxf(m_i[r], mt[r]);
            alpha[r] = __expf(m_i[r] - mnew);
            m_i[r] = mnew;
            float sum = 0.0f;
#pragma unroll
            for (int c = 0; c < 4; c++) {
                float p = __expf(s[r][c] - mnew);
                s[r][c] = p;
                sum += p;
            }
#pragma unroll
            for (int off = 8; off >= 1; off >>= 1)
                sum += __shfl_xor_sync(0xffffffffu, sum, off);
            rs[r] = sum;
            l_i[r] = l_i[r] * alpha[r] + sum;
#pragma unroll
            for (int c = 0; c < 8; c++) o[r][c] *= alpha[r];
        }
        (void)rs;

        __syncthreads();   // all K reads for S done; safe to overwrite with P
#pragma unroll
        for (int r = 0; r < 4; r++) {
            float4 pv;
            pv.x = s[r][0]; pv.y = s[r][1]; pv.z = s[r][2]; pv.w = s[r][3];
            *reinterpret_cast<float4*>(&Ps[(ty * 4 + r) * ALD + tx * 4]) = pv;
        }
        __syncthreads();

        // O += P @ V   (4 rows x 8 cols per thread)
#pragma unroll 4
        for (int kk = 0; kk < 64; kk++) {
            float pr[4];
#pragma unroll
            for (int r = 0; r < 4; r++) pr[r] = Ps[(ty * 4 + r) * ALD + kk];
            float4 v0 = *reinterpret_cast<float4*>(&Vs[kk * ALD + tx * 8]);
            float4 v1 = *reinterpret_cast<float4*>(&Vs[kk * ALD + tx * 8 + 4]);
#pragma unroll
            for (int r = 0; r < 4; r++) {
                o[r][0] += pr[r] * v0.x; o[r][1] += pr[r] * v0.y;
                o[r][2] += pr[r] * v0.z; o[r][3] += pr[r] * v0.w;
                o[r][4] += pr[r] * v1.x; o[r][5] += pr[r] * v1.y;
                o[r][6] += pr[r] * v1.z; o[r][7] += pr[r] * v1.w;
            }
        }
    }

    // finalize: y[b, t, h*128 + d] = O / l
#pragma unroll
    for (int r = 0; r < 4; r++) {
        float inv = 1.0f / l_i[r];
        int t = iq * 64 + ty * 4 + r;
        float* dst = g_ybuf + ((b * T_DIM + t) * C_DIM) + h * HD + tx * 8;
        float4 w0, w1;
        w0.x = o[r][0] * inv; w0.y = o[r][1] * inv;
        w0.z = o[r][2] * inv; w0.w = o[r][3] * inv;
        w1.x = o[r][4] * inv; w1.y = o[r][5] * inv;
        w1.z = o[r][6] * inv; w1.w = o[r][7] * inv;
        *reinterpret_cast<float4*>(&dst[0]) = w0;
        *reinterpret_cast<float4*>(&dst[4]) = w1;
    }
}

// ---------------------------------------------------------------------------
// Out-projection wrapper kernel (A = g_ybuf device global)
// ---------------------------------------------------------------------------
__global__ __launch_bounds__(256) void gemm_out_kernel(
    const float* __restrict__ W, const float* __restrict__ bias,
    float* __restrict__ y)
{
    // delegate to the same body as gemm_nt_kernel<1> but A comes from g_ybuf.
    // (Implemented inline to keep a single compilation unit simple.)
    const float* A = g_ybuf;
    const int K = C_DIM;
    __shared__ float As[GBK][GBM];
    __shared__ float Bs[GBK][GBN];
    const int tid = threadIdx.x;
    const int tx = tid & 15;
    const int ty = tid >> 4;
    const int m0 = blockIdx.y * GBM;
    const int n0 = blockIdx.x * GBN;

    float acc[8][8];
#pragma unroll
    for (int i = 0; i < 8; i++)
#pragma unroll
        for (int j = 0; j < 8; j++) acc[i][j] = 0.0f;

    for (int k0 = 0; k0 < K; k0 += GBK) {
#pragma unroll
        for (int r = 0; r < 2; r++) {
            int idx = tid + r * 256;
            int row = idx >> 2;
            int kq  = (idx & 3) << 2;
            const float4 va = *reinterpret_cast<const float4*>(
                &A[(m0 + row) * K + k0 + kq]);
            As[kq + 0][row] = va.x; As[kq + 1][row] = va.y;
            As[kq + 2][row] = va.z; As[kq + 3][row] = va.w;
            const float4 vb = *reinterpret_cast<const float4*>(
                &W[(n0 + row) * K + k0 + kq]);
            Bs[kq + 0][row] = vb.x; Bs[kq + 1][row] = vb.y;
            Bs[kq + 2][row] = vb.z; Bs[kq + 3][row] = vb.w;
        }
        __syncthreads();
#pragma unroll
        for (int kk = 0; kk < GBK; kk++) {
            float a[8], b[8];
            *reinterpret_cast<float4*>(&a[0]) =
                *reinterpret_cast<float4*>(&As[kk][ty * 8]);
            *reinterpret_cast<float4*>(&a[4]) =
                *reinterpret_cast<float4*>(&As[kk][ty * 8 + 4]);
            *reinterpret_cast<float4*>(&b[0]) =
                *reinterpret_cast<float4*>(&Bs[kk][tx * 8]);
            *reinterpret_cast<float4*>(&b[4]) =
                *reinterpret_cast<float4*>(&Bs[kk][tx * 8 + 4]);
#pragma unroll
            for (int i = 0; i < 8; i++)
#pragma unroll
                for (int j = 0; j < 8; j++) acc[i][j] += a[i] * b[j];
        }
        __syncthreads();
    }

    float bb[8];
#pragma unroll
    for (int j = 0; j < 8; j++) bb[j] = bias[n0 + tx * 8 + j];
#pragma unroll
    for (int i = 0; i < 8; i++) {
        int m = m0 + ty * 8 + i;
        float* dst = y + (size_t)m * C_DIM + n0 + tx * 8;
        float4 r0, r1;
        r0.x = acc[i][0] + bb[0]; r0.y = acc[i][1] + bb[1];
        r0.z = acc[i][2] + bb[2]; r0.w = acc[i][3] + bb[3];
        r1.x = acc[i][4] + bb[4]; r1.y = acc[i][5] + bb[5];
        r1.z = acc[i][6] + bb[6]; r1.w = acc[i][7] + bb[7];
        *reinterpret_cast<float4*>(&dst[0]) = r0;
        *reinterpret_cast<float4*>(&dst[4]) = r1;
    }
}

// ---------------------------------------------------------------------------
extern "C" void kernel_launch(void* const* d_in, const int* in_sizes, int n_in,
                              void* d_out, int out_size)
{
    const float* x    = (const float*)d_in[0];
    const float* Wqkv = (const float*)d_in[1];
    const float* bqkv = (const float*)d_in[2];
    const float* Wout = (const float*)d_in[3];
    const float* bout = (const float*)d_in[4];

    float* y    = (float*)d_out;
    float* kout = y + YELEMS;
    float* vout = y + 2 * YELEMS;

    const int attn_smem = 3 * 64 * ALD * (int)sizeof(float);  // 101376
    cudaFuncSetAttribute(attn_kernel,
                         cudaFuncAttributeMaxDynamicSharedMemorySize, attn_smem);

    // 1) QKV projection + head-layout scatter (q -> scratch, k/v -> output)
    gemm_nt_kernel<0><<<dim3(3 * C_DIM / GBN, MTOT / GBM), 256>>>(
        x, Wqkv, bqkv, kout, vout);

    // 2) causal flash attention -> g_ybuf [B,T,C]
    attn_kernel<<<dim3(T_DIM / 64, B_DIM * NH), 256, attn_smem>>>(kout, vout, 0);

    // 3) output projection -> y
    gemm_out_kernel<<<dim3(C_DIM / GBN, MTOT / GBM), 256>>>(Wout, bout, y);
}

// round 2
// speedup vs baseline: 1.7105x; 1.7105x over previous
#include <cuda_runtime.h>
#include <cstdint>

// Problem shapes (fixed): B=4, T=2048, C=2048, nH=16, hd=128
//   x [B,T,C] f32, Wqkv [3C,C], bqkv [3C], Wout [C,C], bout [C]
// Output = concat(y [B,T,C], new_k [B,nH,T,hd], new_v [B,nH,T,hd])

#define C_DIM   2048
#define T_DIM   2048
#define B_DIM   4
#define NH      16
#define HD      128
#define MTOT    (B_DIM * T_DIM)         // 8192
#define YELEMS  (B_DIM * T_DIM * C_DIM) // 16777216

__device__ float g_qbuf[YELEMS];   // q in [B,nH,T,hd]
__device__ float g_ybuf[YELEMS];   // attention output in [B,T,C]

// ---------------------------------------------------------------------------
// TF32 tensor-core GEMM: C[m,n] = sum_k A[m,k]*W[n,k] + bias[n]
// 128x128x32 tile, 256 threads (8 warps, 2x4), warp tile 64x32,
// m16n8k8 tf32 atoms, smem padded to stride 36 for conflict-free frag LDS.
// MODE 0: QKV projection with q/k/v head-layout scatter epilogue.
// MODE 1: plain row-major [M, 2048] store.
// ---------------------------------------------------------------------------
#define BM 128
#define BN 128
#define BK 32

__device__ __forceinline__ uint32_t f2tf(float f) {
    uint32_t u;
    asm("cvt.rna.tf32.f32 %0, %1;" : "=r"(u) : "f"(f));
    return u;
}

__device__ __forceinline__ void mma_tf32(float* c, const uint32_t* a,
                                         const uint32_t* b) {
    asm volatile(
        "mma.sync.aligned.m16n8k8.row.col.f32.tf32.tf32.f32 "
        "{%0,%1,%2,%3},{%4,%5,%6,%7},{%8,%9},{%0,%1,%2,%3};"
        : "+f"(c[0]), "+f"(c[1]), "+f"(c[2]), "+f"(c[3])
        : "r"(a[0]), "r"(a[1]), "r"(a[2]), "r"(a[3]), "r"(b[0]), "r"(b[1]));
}

template <int MODE>
__global__ __launch_bounds__(256) void mma_gemm(
    const float* __restrict__ A,      // [M, 2048]
    const float* __restrict__ W,      // [N, 2048]
    const float* __restrict__ bias,   // [N]
    float* __restrict__ out0,         // MODE0: k out ; MODE1: y out
    float* __restrict__ out1)         // MODE0: v out ; MODE1: unused
{
    const int K = C_DIM;
    __shared__ uint32_t As[BM][36];
    __shared__ uint32_t Bs[BN][36];

    const int tid  = threadIdx.x;
    const int lane = tid & 31;
    const int wid  = tid >> 5;
    const int wm   = wid >> 2;      // 0..1
    const int wn   = wid & 3;       // 0..3
    const int m0   = blockIdx.y * BM;
    const int n0   = blockIdx.x * BN;

    float acc[4][4][4];
#pragma unroll
    for (int i = 0; i < 4; i++)
#pragma unroll
        for (int j = 0; j < 4; j++)
#pragma unroll
            for (int c = 0; c < 4; c++) acc[i][j][c] = 0.0f;

    float4 pa[4], pb[4];

    // prologue: load tile k0=0
#pragma unroll
    for (int r = 0; r < 4; r++) {
        int idx = tid + r * 256;        // 0..1023
        int row = idx >> 3;             // 0..127
        int kq  = (idx & 7) << 2;       // 0..28
        pa[r] = *reinterpret_cast<const float4*>(&A[(size_t)(m0 + row) * K + kq]);
        pb[r] = *reinterpret_cast<const float4*>(&W[(size_t)(n0 + row) * K + kq]);
    }
#pragma unroll
    for (int r = 0; r < 4; r++) {
        int idx = tid + r * 256;
        int row = idx >> 3;
        int kq  = (idx & 7) << 2;
        As[row][kq + 0] = f2tf(pa[r].x); As[row][kq + 1] = f2tf(pa[r].y);
        As[row][kq + 2] = f2tf(pa[r].z); As[row][kq + 3] = f2tf(pa[r].w);
        Bs[row][kq + 0] = f2tf(pb[r].x); Bs[row][kq + 1] = f2tf(pb[r].y);
        Bs[row][kq + 2] = f2tf(pb[r].z); Bs[row][kq + 3] = f2tf(pb[r].w);
    }
    __syncthreads();

    for (int k0 = 0; k0 < K; k0 += BK) {
        const bool has_next = (k0 + BK) < K;
        if (has_next) {
#pragma unroll
            for (int r = 0; r < 4; r++) {
                int idx = tid + r * 256;
                int row = idx >> 3;
                int kq  = (idx & 7) << 2;
                pa[r] = *reinterpret_cast<const float4*>(
                    &A[(size_t)(m0 + row) * K + k0 + BK + kq]);
                pb[r] = *reinterpret_cast<const float4*>(
                    &W[(size_t)(n0 + row) * K + k0 + BK + kq]);
            }
        }

        // compute on current smem tile: 4 k-steps of 8
#pragma unroll
        for (int ks = 0; ks < 4; ks++) {
            const int kb = ks * 8;
            uint32_t af[4][4], bf[4][2];
#pragma unroll
            for (int am = 0; am < 4; am++) {
                int mr = wm * 64 + am * 16 + (lane >> 2);
                int kc = kb + (lane & 3);
                af[am][0] = As[mr][kc];
                af[am][1] = As[mr + 8][kc];
                af[am][2] = As[mr][kc + 4];
                af[am][3] = As[mr + 8][kc + 4];
            }
#pragma unroll
            for (int an = 0; an < 4; an++) {
                int nr = wn * 32 + an * 8 + (lane >> 2);
                int kc = kb + (lane & 3);
                bf[an][0] = Bs[nr][kc];
                bf[an][1] = Bs[nr][kc + 4];
            }
#pragma unroll
            for (int am = 0; am < 4; am++)
#pragma unroll
                for (int an = 0; an < 4; an++)
                    mma_tf32(acc[am][an], af[am], bf[an]);
        }
        __syncthreads();
        if (has_next) {
#pragma unroll
            for (int r = 0; r < 4; r++) {
                int idx = tid + r * 256;
                int row = idx >> 3;
                int kq  = (idx & 7) << 2;
                As[row][kq + 0] = f2tf(pa[r].x); As[row][kq + 1] = f2tf(pa[r].y);
                As[row][kq + 2] = f2tf(pa[r].z); As[row][kq + 3] = f2tf(pa[r].w);
                Bs[row][kq + 0] = f2tf(pb[r].x); Bs[row][kq + 1] = f2tf(pb[r].y);
                Bs[row][kq + 2] = f2tf(pb[r].z); Bs[row][kq + 3] = f2tf(pb[r].w);
            }
            __syncthreads();
        }
    }

    // ---- epilogue ----
    // c0: (row, col) = (lane>>2, (lane&3)*2), c1: col+1, c2/c3: row+8
    if (MODE == 0) {
        const int seg = n0 >> 11;           // 0=q, 1=k, 2=v
        const int hh  = (n0 & 2047) >> 7;   // head
        float* outp = (seg == 0) ? g_qbuf : ((seg == 1) ? out0 : out1);
#pragma unroll
        for (int am = 0; am < 4; am++) {
#pragma unroll
            for (int cp = 0; cp < 2; cp++) {
                int row = wm * 64 + am * 16 + (lane >> 2) + cp * 8;
                int m = m0 + row;
                int b_ = m >> 11;
                int t  = m & 2047;
                float* dstrow = outp + (((size_t)(b_ * NH + hh) * T_DIM) + t) * HD;
#pragma unroll
                for (int an = 0; an < 4; an++) {
                    int cl = wn * 32 + an * 8 + (lane & 3) * 2;
                    float2 v;
                    v.x = acc[am][an][cp * 2 + 0] + bias[n0 + cl];
                    v.y = acc[am][an][cp * 2 + 1] + bias[n0 + cl + 1];
                    *reinterpret_cast<float2*>(&dstrow[cl]) = v;
                }
            }
        }
    } else {
#pragma unroll
        for (int am = 0; am < 4; am++) {
#pragma unroll
            for (int cp = 0; cp < 2; cp++) {
                int row = wm * 64 + am * 16 + (lane >> 2) + cp * 8;
                int m = m0 + row;
                float* dstrow = out0 + (size_t)m * C_DIM + n0;
#pragma unroll
                for (int an = 0; an < 4; an++) {
                    int cl = wn * 32 + an * 8 + (lane & 3) * 2;
                    float2 v;
                    v.x = acc[am][an][cp * 2 + 0] + bias[n0 + cl];
                    v.y = acc[am][an][cp * 2 + 1] + bias[n0 + cl + 1];
                    *reinterpret_cast<float2*>(&dstrow[cl]) = v;
                }
            }
        }
    }
}

// ---------------------------------------------------------------------------
// Flash attention, causal (unchanged from R1). One block = (b,h, 64-row q tile)
// ---------------------------------------------------------------------------
#define ALD 132

__global__ __launch_bounds__(256, 2) void attn_kernel(
    const float* __restrict__ Kt,   // [B,nH,T,hd]
    const float* __restrict__ Vt,   // [B,nH,T,hd]
    int dummy)
{
    extern __shared__ float smem[];
    float* Qs = smem;
    float* Ks = smem + 64 * ALD;
    float* Vs = smem + 2 * 64 * ALD;
    float* Ps = Ks;

    const int tid = threadIdx.x;
    const int tx = tid & 15;
    const int ty = tid >> 4;
    const int iq = blockIdx.x;
    const int bh = blockIdx.y;
    const int b  = bh >> 4;
    const int h  = bh & 15;

    const float* qp = g_qbuf + ((bh * T_DIM) + iq * 64) * HD;
    const float* kp = Kt + (size_t)bh * T_DIM * HD;
    const float* vp = Vt + (size_t)bh * T_DIM * HD;

#pragma unroll
    for (int r = 0; r < 8; r++) {
        int idx = tid + r * 256;
        int row = idx >> 5;
        int c   = (idx & 31) << 2;
        *reinterpret_cast<float4*>(&Qs[row * ALD + c]) =
            *reinterpret_cast<const float4*>(&qp[row * HD + c]);
    }

    float m_i[4], l_i[4], o[4][8];
#pragma unroll
    for (int r = 0; r < 4; r++) {
        m_i[r] = -1e30f; l_i[r] = 0.0f;
#pragma unroll
        for (int c = 0; c < 8; c++) o[r][c] = 0.0f;
    }

    const float scale = 0.08838834764831843f;

    for (int j = 0; j <= iq; j++) {
        __syncthreads();
        const float* kb = kp + j * 64 * HD;
        const float* vb = vp + j * 64 * HD;
#pragma unroll
        for (int r = 0; r < 8; r++) {
            int idx = tid + r * 256;
            int row = idx >> 5;
            int c   = (idx & 31) << 2;
            *reinterpret_cast<float4*>(&Ks[row * ALD + c]) =
                *reinterpret_cast<const float4*>(&kb[row * HD + c]);
            *reinterpret_cast<float4*>(&Vs[row * ALD + c]) =
                *reinterpret_cast<const float4*>(&vb[row * HD + c]);
        }
        __syncthreads();

        float s[4][4];
#pragma unroll
        for (int r = 0; r < 4; r++)
#pragma unroll
            for (int c = 0; c < 4; c++) s[r][c] = 0.0f;

        for (int d = 0; d < HD; d += 4) {
            float4 qv[4], kv[4];
#pragma unroll
            for (int r = 0; r < 4; r++)
                qv[r] = *reinterpret_cast<float4*>(&Qs[(ty * 4 + r) * ALD + d]);
#pragma unroll
            for (int c = 0; c < 4; c++)
                kv[c] = *reinterpret_cast<float4*>(&Ks[(tx * 4 + c) * ALD + d]);
#pragma unroll
            for (int r = 0; r < 4; r++)
#pragma unroll
                for (int c = 0; c < 4; c++) {
                    s[r][c] += qv[r].x * kv[c].x + qv[r].y * kv[c].y
                             + qv[r].z * kv[c].z + qv[r].w * kv[c].w;
                }
        }

#pragma unroll
        for (int r = 0; r < 4; r++)
#pragma unroll
            for (int c = 0; c < 4; c++) s[r][c] *= scale;

        if (j == iq) {
#pragma unroll
            for (int r = 0; r < 4; r++)
#pragma unroll
                for (int c = 0; c < 4; c++)
                    if (tx * 4 + c > ty * 4 + r) s[r][c] = -1e30f;
        }

        float mt[4], alpha[4];
#pragma unroll
        for (int r = 0; r < 4; r++) {
            float mx = s[r][0];
            mx = fmaxf(mx, s[r][1]); mx = fmaxf(mx, s[r][2]); mx = fmaxf(mx, s[r][3]);
#pragma unroll
            for (int off = 8; off >= 1; off >>= 1)
                mx = fmaxf(mx, __shfl_xor_sync(0xffffffffu, mx, off));
            mt[r] = mx;
        }
#pragma unroll
        for (int r = 0; r < 4; r++) {
            float mnew = fmaxf(m_i[r], mt[r]);
            alpha[r] = __expf(m_i[r] - mnew);
            m_i[r] = mnew;
            float sum = 0.0f;
#pragma unroll
            for (int c = 0; c < 4; c++) {
                float p = __expf(s[r][c] - mnew);
                s[r][c] = p;
                sum += p;
            }
#pragma unroll
            for (int off = 8; off >= 1; off >>= 1)
                sum += __shfl_xor_sync(0xffffffffu, sum, off);
            l_i[r] = l_i[r] * alpha[r] + sum;
#pragma unroll
            for (int c = 0; c < 8; c++) o[r][c] *= alpha[r];
        }

        __syncthreads();
#pragma unroll
        for (int r = 0; r < 4; r++) {
            float4 pv;
            pv.x = s[r][0]; pv.y = s[r][1]; pv.z = s[r][2]; pv.w = s[r][3];
            *reinterpret_cast<float4*>(&Ps[(ty * 4 + r) * ALD + tx * 4]) = pv;
        }
        __syncthreads();

#pragma unroll 4
        for (int kk = 0; kk < 64; kk++) {
            float pr[4];
#pragma unroll
            for (int r = 0; r < 4; r++) pr[r] = Ps[(ty * 4 + r) * ALD + kk];
            float4 v0 = *reinterpret_cast<float4*>(&Vs[kk * ALD + tx * 8]);
            float4 v1 = *reinterpret_cast<float4*>(&Vs[kk * ALD + tx * 8 + 4]);
#pragma unroll
            for (int r = 0; r < 4; r++) {
                o[r][0] += pr[r] * v0.x; o[r][1] += pr[r] * v0.y;
                o[r][2] += pr[r] * v0.z; o[r][3] += pr[r] * v0.w;
                o[r][4] += pr[r] * v1.x; o[r][5] += pr[r] * v1.y;
                o[r][6] += pr[r] * v1.z; o[r][7] += pr[r] * v1.w;
            }
        }
    }

#pragma unroll
    for (int r = 0; r < 4; r++) {
        float inv = 1.0f / l_i[r];
        int t = iq * 64 + ty * 4 + r;
        float* dst = g_ybuf + ((size_t)(b * T_DIM + t) * C_DIM) + h * HD + tx * 8;
        float4 w0, w1;
        w0.x = o[r][0] * inv; w0.y = o[r][1] * inv;
        w0.z = o[r][2] * inv; w0.w = o[r][3] * inv;
        w1.x = o[r][4] * inv; w1.y = o[r][5] * inv;
        w1.z = o[r][6] * inv; w1.w = o[r][7] * inv;
        *reinterpret_cast<float4*>(&dst[0]) = w0;
        *reinterpret_cast<float4*>(&dst[4]) = w1;
    }
}

// ---------------------------------------------------------------------------
extern "C" void kernel_launch(void* const* d_in, const int* in_sizes, int n_in,
                              void* d_out, int out_size)
{
    const float* x    = (const float*)d_in[0];
    const float* Wqkv = (const float*)d_in[1];
    const float* bqkv = (const float*)d_in[2];
    const float* Wout = (const float*)d_in[3];
    const float* bout = (const float*)d_in[4];

    float* y    = (float*)d_out;
    float* kout = y + YELEMS;
    float* vout = y + 2 * YELEMS;

    float* ybuf = nullptr;
    cudaGetSymbolAddress((void**)&ybuf, g_ybuf);

    const int attn_smem = 3 * 64 * ALD * (int)sizeof(float);  // 101376
    cudaFuncSetAttribute(attn_kernel,
                         cudaFuncAttributeMaxDynamicSharedMemorySize, attn_smem);

    // 1) QKV projection (tf32 MMA) + head-layout scatter
    mma_gemm<0><<<dim3(3 * C_DIM / BN, MTOT / BM), 256>>>(
        x, Wqkv, bqkv, kout, vout);

    // 2) causal flash attention -> g_ybuf [B,T,C]
    attn_kernel<<<dim3(T_DIM / 64, B_DIM * NH), 256, attn_smem>>>(kout, vout, 0);

    // 3) output projection (tf32 MMA) -> y
    mma_gemm<1><<<dim3(C_DIM / BN, MTOT / BM), 256>>>(
        ybuf, Wout, bout, y, nullptr);
}

// round 3
// speedup vs baseline: 3.6212x; 2.1170x over previous
#include <cuda_runtime.h>
#include <cstdint>

// Problem shapes (fixed): B=4, T=2048, C=2048, nH=16, hd=128
// Output = concat(y [B,T,C], new_k [B,nH,T,hd], new_v [B,nH,T,hd])

#define C_DIM   2048
#define T_DIM   2048
#define B_DIM   4
#define NH      16
#define HD      128
#define MTOT    (B_DIM * T_DIM)         // 8192
#define YELEMS  (B_DIM * T_DIM * C_DIM) // 16777216

__device__ float g_qbuf[YELEMS];   // q in [B,nH,T,hd]
__device__ float g_ybuf[YELEMS];   // attention output in [B,T,C]

__device__ __forceinline__ uint32_t f2tf(float f) {
    uint32_t u;
    asm("cvt.rna.tf32.f32 %0, %1;" : "=r"(u) : "f"(f));
    return u;
}

__device__ __forceinline__ void mma_tf32(float* c, const uint32_t* a,
                                         const uint32_t* b) {
    asm volatile(
        "mma.sync.aligned.m16n8k8.row.col.f32.tf32.tf32.f32 "
        "{%0,%1,%2,%3},{%4,%5,%6,%7},{%8,%9},{%0,%1,%2,%3};"
        : "+f"(c[0]), "+f"(c[1]), "+f"(c[2]), "+f"(c[3])
        : "r"(a[0]), "r"(a[1]), "r"(a[2]), "r"(a[3]), "r"(b[0]), "r"(b[1]));
}

// ---------------------------------------------------------------------------
// TF32 tensor-core projection GEMM (unchanged from R2)
// ---------------------------------------------------------------------------
#define BM 128
#define BN 128
#define BK 32

template <int MODE>
__global__ __launch_bounds__(256) void mma_gemm(
    const float* __restrict__ A,
    const float* __restrict__ W,
    const float* __restrict__ bias,
    float* __restrict__ out0,
    float* __restrict__ out1)
{
    const int K = C_DIM;
    __shared__ uint32_t As[BM][36];
    __shared__ uint32_t Bs[BN][36];

    const int tid  = threadIdx.x;
    const int lane = tid & 31;
    const int wid  = tid >> 5;
    const int wm   = wid >> 2;
    const int wn   = wid & 3;
    const int m0   = blockIdx.y * BM;
    const int n0   = blockIdx.x * BN;

    float acc[4][4][4];
#pragma unroll
    for (int i = 0; i < 4; i++)
#pragma unroll
        for (int j = 0; j < 4; j++)
#pragma unroll
            for (int c = 0; c < 4; c++) acc[i][j][c] = 0.0f;

    float4 pa[4], pb[4];
#pragma unroll
    for (int r = 0; r < 4; r++) {
        int idx = tid + r * 256;
        int row = idx >> 3;
        int kq  = (idx & 7) << 2;
        pa[r] = *reinterpret_cast<const float4*>(&A[(size_t)(m0 + row) * K + kq]);
        pb[r] = *reinterpret_cast<const float4*>(&W[(size_t)(n0 + row) * K + kq]);
    }
#pragma unroll
    for (int r = 0; r < 4; r++) {
        int idx = tid + r * 256;
        int row = idx >> 3;
        int kq  = (idx & 7) << 2;
        As[row][kq + 0] = f2tf(pa[r].x); As[row][kq + 1] = f2tf(pa[r].y);
        As[row][kq + 2] = f2tf(pa[r].z); As[row][kq + 3] = f2tf(pa[r].w);
        Bs[row][kq + 0] = f2tf(pb[r].x); Bs[row][kq + 1] = f2tf(pb[r].y);
        Bs[row][kq + 2] = f2tf(pb[r].z); Bs[row][kq + 3] = f2tf(pb[r].w);
    }
    __syncthreads();

    for (int k0 = 0; k0 < K; k0 += BK) {
        const bool has_next = (k0 + BK) < K;
        if (has_next) {
#pragma unroll
            for (int r = 0; r < 4; r++) {
                int idx = tid + r * 256;
                int row = idx >> 3;
                int kq  = (idx & 7) << 2;
                pa[r] = *reinterpret_cast<const float4*>(
                    &A[(size_t)(m0 + row) * K + k0 + BK + kq]);
                pb[r] = *reinterpret_cast<const float4*>(
                    &W[(size_t)(n0 + row) * K + k0 + BK + kq]);
            }
        }
#pragma unroll
        for (int ks = 0; ks < 4; ks++) {
            const int kb = ks * 8;
            uint32_t af[4][4], bf[4][2];
#pragma unroll
            for (int am = 0; am < 4; am++) {
                int mr = wm * 64 + am * 16 + (lane >> 2);
                int kc = kb + (lane & 3);
                af[am][0] = As[mr][kc];
                af[am][1] = As[mr + 8][kc];
                af[am][2] = As[mr][kc + 4];
                af[am][3] = As[mr + 8][kc + 4];
            }
#pragma unroll
            for (int an = 0; an < 4; an++) {
                int nr = wn * 32 + an * 8 + (lane >> 2);
                int kc = kb + (lane & 3);
                bf[an][0] = Bs[nr][kc];
                bf[an][1] = Bs[nr][kc + 4];
            }
#pragma unroll
            for (int am = 0; am < 4; am++)
#pragma unroll
                for (int an = 0; an < 4; an++)
                    mma_tf32(acc[am][an], af[am], bf[an]);
        }
        __syncthreads();
        if (has_next) {
#pragma unroll
            for (int r = 0; r < 4; r++) {
                int idx = tid + r * 256;
                int row = idx >> 3;
                int kq  = (idx & 7) << 2;
                As[row][kq + 0] = f2tf(pa[r].x); As[row][kq + 1] = f2tf(pa[r].y);
                As[row][kq + 2] = f2tf(pa[r].z); As[row][kq + 3] = f2tf(pa[r].w);
                Bs[row][kq + 0] = f2tf(pb[r].x); Bs[row][kq + 1] = f2tf(pb[r].y);
                Bs[row][kq + 2] = f2tf(pb[r].z); Bs[row][kq + 3] = f2tf(pb[r].w);
            }
            __syncthreads();
        }
    }

    if (MODE == 0) {
        const int seg = n0 >> 11;
        const int hh  = (n0 & 2047) >> 7;
        float* outp = (seg == 0) ? g_qbuf : ((seg == 1) ? out0 : out1);
#pragma unroll
        for (int am = 0; am < 4; am++) {
#pragma unroll
            for (int cp = 0; cp < 2; cp++) {
                int row = wm * 64 + am * 16 + (lane >> 2) + cp * 8;
                int m = m0 + row;
                int b_ = m >> 11;
                int t  = m & 2047;
                float* dstrow = outp + (((size_t)(b_ * NH + hh) * T_DIM) + t) * HD;
#pragma unroll
                for (int an = 0; an < 4; an++) {
                    int cl = wn * 32 + an * 8 + (lane & 3) * 2;
                    float2 v;
                    v.x = acc[am][an][cp * 2 + 0] + bias[n0 + cl];
                    v.y = acc[am][an][cp * 2 + 1] + bias[n0 + cl + 1];
                    *reinterpret_cast<float2*>(&dstrow[cl]) = v;
                }
            }
        }
    } else {
#pragma unroll
        for (int am = 0; am < 4; am++) {
#pragma unroll
            for (int cp = 0; cp < 2; cp++) {
                int row = wm * 64 + am * 16 + (lane >> 2) + cp * 8;
                int m = m0 + row;
                float* dstrow = out0 + (size_t)m * C_DIM + n0;
#pragma unroll
                for (int an = 0; an < 4; an++) {
                    int cl = wn * 32 + an * 8 + (lane & 3) * 2;
                    float2 v;
                    v.x = acc[am][an][cp * 2 + 0] + bias[n0 + cl];
                    v.y = acc[am][an][cp * 2 + 1] + bias[n0 + cl + 1];
                    *reinterpret_cast<float2*>(&dstrow[cl]) = v;
                }
            }
        }
    }
}

// ---------------------------------------------------------------------------
// TF32 MMA flash attention, causal.
// BQ=128, BK=64, 256 threads (8 warps), warp owns 16 q-rows.
// Strides: Qs/Ks 132 (conflict-free A/B frags), Vs 136 (conflict-free PV B),
// Ps 68 (conflict-free PV A). P produced+consumed by same warp -> __syncwarp.
// ---------------------------------------------------------------------------
#define AQ_LD 132
#define AV_LD 136
#define AP_LD 68

__global__ __launch_bounds__(256, 1) void attn_mma_kernel(
    const float* __restrict__ Kt,   // [B,nH,T,hd]
    const float* __restrict__ Vt)   // [B,nH,T,hd]
{
    extern __shared__ uint32_t sm[];
    uint32_t* Qs = sm;                        // 128 x 132
    uint32_t* Ks = Qs + 128 * AQ_LD;          // 64 x 132
    uint32_t* Vs = Ks + 64 * AQ_LD;           // 64 x 136
    uint32_t* Ps = Vs + 64 * AV_LD;           // 128 x 68

    const int tid  = threadIdx.x;
    const int lane = tid & 31;
    const int w    = tid >> 5;        // 0..7, warp owns rows [w*16, w*16+16)
    const int iq   = blockIdx.x;      // q tile (128 rows), 0..15
    const int bh   = blockIdx.y;      // 0..63
    const int b    = bh >> 4;
    const int h    = bh & 15;

    const float* qp = g_qbuf + ((size_t)bh * T_DIM + iq * 128) * HD;
    const float* kp = Kt + (size_t)bh * T_DIM * HD;
    const float* vp = Vt + (size_t)bh * T_DIM * HD;

    // load Q tile (128 x 128) -> tf32
#pragma unroll
    for (int r = 0; r < 16; r++) {
        int idx = tid + r * 256;
        int row = idx >> 5;
        int c   = (idx & 31) << 2;
        float4 v = *reinterpret_cast<const float4*>(&qp[row * HD + c]);
        Qs[row * AQ_LD + c + 0] = f2tf(v.x);
        Qs[row * AQ_LD + c + 1] = f2tf(v.y);
        Qs[row * AQ_LD + c + 2] = f2tf(v.z);
        Qs[row * AQ_LD + c + 3] = f2tf(v.w);
    }

    const int r0 = lane >> 2;          // row in warp tile (and +8)
    float m_i[2] = {-1e30f, -1e30f};
    float l_i[2] = {0.0f, 0.0f};
    float oacc[16][4];
#pragma unroll
    for (int na = 0; na < 16; na++)
#pragma unroll
        for (int c = 0; c < 4; c++) oacc[na][c] = 0.0f;

    const float scale = 0.08838834764831843f;  // 1/sqrt(128)
    const int jmax = 2 * iq + 1;

    for (int j = 0; j <= jmax; j++) {
        __syncthreads();
        const float* kb = kp + (size_t)j * 64 * HD;
        const float* vb = vp + (size_t)j * 64 * HD;
#pragma unroll
        for (int r = 0; r < 8; r++) {
            int idx = tid + r * 256;
            int row = idx >> 5;
            int c   = (idx & 31) << 2;
            float4 kv = *reinterpret_cast<const float4*>(&kb[row * HD + c]);
            Ks[row * AQ_LD + c + 0] = f2tf(kv.x);
            Ks[row * AQ_LD + c + 1] = f2tf(kv.y);
            Ks[row * AQ_LD + c + 2] = f2tf(kv.z);
            Ks[row * AQ_LD + c + 3] = f2tf(kv.w);
            float4 vv = *reinterpret_cast<const float4*>(&vb[row * HD + c]);
            Vs[row * AV_LD + c + 0] = f2tf(vv.x);
            Vs[row * AV_LD + c + 1] = f2tf(vv.y);
            Vs[row * AV_LD + c + 2] = f2tf(vv.z);
            Vs[row * AV_LD + c + 3] = f2tf(vv.w);
        }
        __syncthreads();

        // S = Q K^T   (warp tile 16 x 64)
        float sacc[8][4];
#pragma unroll
        for (int na = 0; na < 8; na++)
#pragma unroll
            for (int c = 0; c < 4; c++) sacc[na][c] = 0.0f;

#pragma unroll
        for (int ks = 0; ks < 16; ks++) {
            int kc = ks * 8 + (lane & 3);
            uint32_t af[4];
            int mr = w * 16 + r0;
            af[0] = Qs[mr * AQ_LD + kc];
            af[1] = Qs[(mr + 8) * AQ_LD + kc];
            af[2] = Qs[mr * AQ_LD + kc + 4];
            af[3] = Qs[(mr + 8) * AQ_LD + kc + 4];
#pragma unroll
            for (int na = 0; na < 8; na++) {
                uint32_t bf[2];
                int nr = na * 8 + r0;
                bf[0] = Ks[nr * AQ_LD + kc];
                bf[1] = Ks[nr * AQ_LD + kc + 4];
                mma_tf32(sacc[na], af, bf);
            }
        }

        // scale + causal mask (only the two diagonal-straddling tiles)
#pragma unroll
        for (int na = 0; na < 8; na++)
#pragma unroll
            for (int c = 0; c < 4; c++) sacc[na][c] *= scale;
        if (j >= 2 * iq) {
            int qrow0 = iq * 128 + w * 16 + r0;
#pragma unroll
            for (int na = 0; na < 8; na++) {
                int col = j * 64 + na * 8 + 2 * (lane & 3);
                if (col > qrow0)     sacc[na][0] = -1e30f;
                if (col + 1 > qrow0) sacc[na][1] = -1e30f;
                if (col > qrow0 + 8)     sacc[na][2] = -1e30f;
                if (col + 1 > qrow0 + 8) sacc[na][3] = -1e30f;
            }
        }

        // online softmax (rows r0, r0+8)
        float mt[2] = {-1e30f, -1e30f};
#pragma unroll
        for (int na = 0; na < 8; na++) {
            mt[0] = fmaxf(mt[0], fmaxf(sacc[na][0], sacc[na][1]));
            mt[1] = fmaxf(mt[1], fmaxf(sacc[na][2], sacc[na][3]));
        }
#pragma unroll
        for (int off = 1; off <= 2; off <<= 1) {
            mt[0] = fmaxf(mt[0], __shfl_xor_sync(0xffffffffu, mt[0], off));
            mt[1] = fmaxf(mt[1], __shfl_xor_sync(0xffffffffu, mt[1], off));
        }
        float mnew0 = fmaxf(m_i[0], mt[0]);
        float mnew1 = fmaxf(m_i[1], mt[1]);
        float alpha0 = __expf(m_i[0] - mnew0);
        float alpha1 = __expf(m_i[1] - mnew1);
        m_i[0] = mnew0; m_i[1] = mnew1;

        float sum0 = 0.0f, sum1 = 0.0f;
#pragma unroll
        for (int na = 0; na < 8; na++) {
            float p0 = __expf(sacc[na][0] - mnew0);
            float p1 = __expf(sacc[na][1] - mnew0);
            float p2 = __expf(sacc[na][2] - mnew1);
            float p3 = __expf(sacc[na][3] - mnew1);
            sum0 += p0 + p1; sum1 += p2 + p3;
            int prow = w * 16 + r0;
            int pcol = na * 8 + 2 * (lane & 3);
            uint2 pv0 = make_uint2(f2tf(p0), f2tf(p1));
            uint2 pv1 = make_uint2(f2tf(p2), f2tf(p3));
            *reinterpret_cast<uint2*>(&Ps[prow * AP_LD + pcol]) = pv0;
            *reinterpret_cast<uint2*>(&Ps[(prow + 8) * AP_LD + pcol]) = pv1;
        }
#pragma unroll
        for (int off = 1; off <= 2; off <<= 1) {
            sum0 += __shfl_xor_sync(0xffffffffu, sum0, off);
            sum1 += __shfl_xor_sync(0xffffffffu, sum1, off);
        }
        l_i[0] = l_i[0] * alpha0 + sum0;
        l_i[1] = l_i[1] * alpha1 + sum1;
#pragma unroll
        for (int na = 0; na < 16; na++) {
            oacc[na][0] *= alpha0; oacc[na][1] *= alpha0;
            oacc[na][2] *= alpha1; oacc[na][3] *= alpha1;
        }

        __syncwarp();

        // O += P @ V   (warp tile 16 x 128, K=64)
#pragma unroll
        for (int ks = 0; ks < 8; ks++) {
            int kc = ks * 8 + (lane & 3);
            uint32_t af[4];
            int mr = w * 16 + r0;
            af[0] = Ps[mr * AP_LD + kc];
            af[1] = Ps[(mr + 8) * AP_LD + kc];
            af[2] = Ps[mr * AP_LD + kc + 4];
            af[3] = Ps[(mr + 8) * AP_LD + kc + 4];
#pragma unroll
            for (int na = 0; na < 16; na++) {
                uint32_t bf[2];
                bf[0] = Vs[kc * AV_LD + na * 8 + r0];
                bf[1] = Vs[(kc + 4) * AV_LD + na * 8 + r0];
                mma_tf32(oacc[na], af, bf);
            }
        }
        __syncwarp();
    }

    // finalize
    float inv0 = 1.0f / l_i[0];
    float inv1 = 1.0f / l_i[1];
    int t0 = iq * 128 + w * 16 + r0;
    int t1 = t0 + 8;
    float* dst0 = g_ybuf + ((size_t)(b * T_DIM + t0) * C_DIM) + h * HD;
    float* dst1 = g_ybuf + ((size_t)(b * T_DIM + t1) * C_DIM) + h * HD;
#pragma unroll
    for (int na = 0; na < 16; na++) {
        int col = na * 8 + 2 * (lane & 3);
        float2 v0, v1;
        v0.x = oacc[na][0] * inv0; v0.y = oacc[na][1] * inv0;
        v1.x = oacc[na][2] * inv1; v1.y = oacc[na][3] * inv1;
        *reinterpret_cast<float2*>(&dst0[col]) = v0;
        *reinterpret_cast<float2*>(&dst1[col]) = v1;
    }
}

// ---------------------------------------------------------------------------
extern "C" void kernel_launch(void* const* d_in, const int* in_sizes, int n_in,
                              void* d_out, int out_size)
{
    const float* x    = (const float*)d_in[0];
    const float* Wqkv = (const float*)d_in[1];
    const float* bqkv = (const float*)d_in[2];
    const float* Wout = (const float*)d_in[3];
    const float* bout = (const float*)d_in[4];

    float* y    = (float*)d_out;
    float* kout = y + YELEMS;
    float* vout = y + 2 * YELEMS;

    float* ybuf = nullptr;
    cudaGetSymbolAddress((void**)&ybuf, g_ybuf);

    const int attn_smem =
        (128 * AQ_LD + 64 * AQ_LD + 64 * AV_LD + 128 * AP_LD) * 4;  // 171008
    cudaFuncSetAttribute(attn_mma_kernel,
                         cudaFuncAttributeMaxDynamicSharedMemorySize, attn_smem);

    // 1) QKV projection (tf32 MMA) + head-layout scatter
    mma_gemm<0><<<dim3(3 * C_DIM / BN, MTOT / BM), 256>>>(
        x, Wqkv, bqkv, kout, vout);

    // 2) causal flash attention (tf32 MMA) -> g_ybuf [B,T,C]
    attn_mma_kernel<<<dim3(T_DIM / 128, B_DIM * NH), 256, attn_smem>>>(
        kout, vout);

    // 3) output projection (tf32 MMA) -> y
    mma_gemm<1><<<dim3(C_DIM / BN, MTOT / BM), 256>>>(
        ybuf, Wout, bout, y, nullptr);
}

// round 4
// speedup vs baseline: 4.2867x; 1.1838x over previous
#include <cuda_runtime.h>
#include <cstdint>

// Shapes (fixed): B=4, T=2048, C=2048, nH=16, hd=128
// Output = concat(y [B,T,C], new_k [B,nH,T,hd], new_v [B,nH,T,hd])

#define C_DIM   2048
#define T_DIM   2048
#define B_DIM   4
#define NH      16
#define HD      128
#define MTOT    (B_DIM * T_DIM)         // 8192
#define YELEMS  (B_DIM * T_DIM * C_DIM) // 16777216

// tf32 staging buffers (values stored as tf32-rounded fp32 bit patterns)
__device__ uint32_t g_xtf[YELEMS];              // x
__device__ uint32_t g_wqkvtf[3 * C_DIM * C_DIM];
__device__ uint32_t g_wouttf[C_DIM * C_DIM];
__device__ uint32_t g_qbuf[YELEMS];             // q in [B,nH,T,hd], tf32
__device__ uint32_t g_ybuf[YELEMS];             // attn out [B,T,C], tf32

__device__ __forceinline__ uint32_t f2tf(float f) {
    uint32_t u;
    asm("cvt.rna.tf32.f32 %0, %1;" : "=r"(u) : "f"(f));
    return u;
}

__device__ __forceinline__ void mma_tf32(float* c, const uint32_t* a,
                                         const uint32_t* b) {
    asm volatile(
        "mma.sync.aligned.m16n8k8.row.col.f32.tf32.tf32.f32 "
        "{%0,%1,%2,%3},{%4,%5,%6,%7},{%8,%9},{%0,%1,%2,%3};"
        : "+f"(c[0]), "+f"(c[1]), "+f"(c[2]), "+f"(c[3])
        : "r"(a[0]), "r"(a[1]), "r"(a[2]), "r"(a[3]), "r"(b[0]), "r"(b[1]));
}

__device__ __forceinline__ void cpasync16(uint32_t smem_addr, const void* g) {
    asm volatile("cp.async.cg.shared.global [%0], [%1], 16;"
                 :: "r"(smem_addr), "l"(g));
}

// ---------------------------------------------------------------------------
// fp32 -> tf32 conversion pass (vectorized, grid-stride)
// ---------------------------------------------------------------------------
__global__ __launch_bounds__(256) void cvt_tf32_kernel(
    const float4* __restrict__ src, uint4* __restrict__ dst, int n4)
{
    for (int i = blockIdx.x * blockDim.x + threadIdx.x; i < n4;
         i += gridDim.x * blockDim.x) {
        float4 v = src[i];
        uint4 u;
        u.x = f2tf(v.x); u.y = f2tf(v.y); u.z = f2tf(v.z); u.w = f2tf(v.w);
        dst[i] = u;
    }
}

// ---------------------------------------------------------------------------
// TF32 GEMM, cp.async double-buffered. C[m,n] = sum_k A[m,k]*W[n,k] + bias[n]
// 128x128x32 tile, 256 threads, warp tile 64x32, m16n8k8.
// MODE 0: QKV proj (q->g_qbuf tf32, k/v->fp32 outputs, head scatter)
// MODE 1: out proj (fp32 row-major store)
// ---------------------------------------------------------------------------
#define BM 128
#define BN 128
#define BK 32

template <int MODE>
__global__ __launch_bounds__(256, 2) void mma_gemm(
    const uint32_t* __restrict__ A,   // [M,2048] tf32
    const uint32_t* __restrict__ W,   // [N,2048] tf32
    const float* __restrict__ bias,
    float* __restrict__ out0,         // MODE0: k ; MODE1: y
    float* __restrict__ out1)         // MODE0: v
{
    const int K = C_DIM;
    __shared__ uint32_t As[2][BM][36];
    __shared__ uint32_t Bs[2][BN][36];

    const int tid  = threadIdx.x;
    const int lane = tid & 31;
    const int wid  = tid >> 5;
    const int wm   = wid >> 2;
    const int wn   = wid & 3;
    const int m0   = blockIdx.y * BM;
    const int n0   = blockIdx.x * BN;

    // per-thread copy slice: 4 chunks of 16B per matrix
    const int crow = tid >> 3;            // 0..31 (+32*r)
    const int ckq  = (tid & 7) << 2;      // 0,4,...,28

    float acc[4][4][4];
#pragma unroll
    for (int i = 0; i < 4; i++)
#pragma unroll
        for (int j = 0; j < 4; j++)
#pragma unroll
            for (int c = 0; c < 4; c++) acc[i][j][c] = 0.0f;

    // prologue: async-load tile 0 into buffer 0
#pragma unroll
    for (int r = 0; r < 4; r++) {
        int row = crow + r * 32;
        cpasync16((uint32_t)__cvta_generic_to_shared(&As[0][row][ckq]),
                  &A[(size_t)(m0 + row) * K + ckq]);
        cpasync16((uint32_t)__cvta_generic_to_shared(&Bs[0][row][ckq]),
                  &W[(size_t)(n0 + row) * K + ckq]);
    }
    asm volatile("cp.async.commit_group;");

    int buf = 0;
    for (int k0 = 0; k0 < K; k0 += BK) {
        const bool has_next = (k0 + BK) < K;
        if (has_next) {
#pragma unroll
            for (int r = 0; r < 4; r++) {
                int row = crow + r * 32;
                cpasync16((uint32_t)__cvta_generic_to_shared(&As[buf ^ 1][row][ckq]),
                          &A[(size_t)(m0 + row) * K + k0 + BK + ckq]);
                cpasync16((uint32_t)__cvta_generic_to_shared(&Bs[buf ^ 1][row][ckq]),
                          &W[(size_t)(n0 + row) * K + k0 + BK + ckq]);
            }
            asm volatile("cp.async.commit_group;");
            asm volatile("cp.async.wait_group 1;");
        } else {
            asm volatile("cp.async.wait_group 0;");
        }
        __syncthreads();

#pragma unroll
        for (int ks = 0; ks < 4; ks++) {
            const int kb = ks * 8;
            uint32_t af[4][4], bf[4][2];
#pragma unroll
            for (int am = 0; am < 4; am++) {
                int mr = wm * 64 + am * 16 + (lane >> 2);
                int kc = kb + (lane & 3);
                af[am][0] = As[buf][mr][kc];
                af[am][1] = As[buf][mr + 8][kc];
                af[am][2] = As[buf][mr][kc + 4];
                af[am][3] = As[buf][mr + 8][kc + 4];
            }
#pragma unroll
            for (int an = 0; an < 4; an++) {
                int nr = wn * 32 + an * 8 + (lane >> 2);
                int kc = kb + (lane & 3);
                bf[an][0] = Bs[buf][nr][kc];
                bf[an][1] = Bs[buf][nr][kc + 4];
            }
#pragma unroll
            for (int am = 0; am < 4; am++)
#pragma unroll
                for (int an = 0; an < 4; an++)
                    mma_tf32(acc[am][an], af[am], bf[an]);
        }
        buf ^= 1;
        __syncthreads();   // compute done before next issue overwrites this buf
    }

    // ---- epilogue ----
    if (MODE == 0) {
        const int seg = n0 >> 11;           // 0=q, 1=k, 2=v
        const int hh  = (n0 & 2047) >> 7;
#pragma unroll
        for (int am = 0; am < 4; am++) {
#pragma unroll
            for (int cp = 0; cp < 2; cp++) {
                int row = wm * 64 + am * 16 + (lane >> 2) + cp * 8;
                int m = m0 + row;
                int b_ = m >> 11;
                int t  = m & 2047;
                size_t base = (((size_t)(b_ * NH + hh) * T_DIM) + t) * HD;
                if (seg == 0) {
                    uint32_t* dstrow = g_qbuf + base;
#pragma unroll
                    for (int an = 0; an < 4; an++) {
                        int cl = wn * 32 + an * 8 + (lane & 3) * 2;
                        uint2 v;
                        v.x = f2tf(acc[am][an][cp * 2 + 0] + bias[n0 + cl]);
                        v.y = f2tf(acc[am][an][cp * 2 + 1] + bias[n0 + cl + 1]);
                        *reinterpret_cast<uint2*>(&dstrow[cl]) = v;
                    }
                } else {
                    float* dstrow = ((seg == 1) ? out0 : out1) + base;
#pragma unroll
                    for (int an = 0; an < 4; an++) {
                        int cl = wn * 32 + an * 8 + (lane & 3) * 2;
                        float2 v;
                        v.x = acc[am][an][cp * 2 + 0] + bias[n0 + cl];
                        v.y = acc[am][an][cp * 2 + 1] + bias[n0 + cl + 1];
                        *reinterpret_cast<float2*>(&dstrow[cl]) = v;
                    }
                }
            }
        }
    } else {
#pragma unroll
        for (int am = 0; am < 4; am++) {
#pragma unroll
            for (int cp = 0; cp < 2; cp++) {
                int row = wm * 64 + am * 16 + (lane >> 2) + cp * 8;
                int m = m0 + row;
                float* dstrow = out0 + (size_t)m * C_DIM + n0;
#pragma unroll
                for (int an = 0; an < 4; an++) {
                    int cl = wn * 32 + an * 8 + (lane & 3) * 2;
                    float2 v;
                    v.x = acc[am][an][cp * 2 + 0] + bias[n0 + cl];
                    v.y = acc[am][an][cp * 2 + 1] + bias[n0 + cl + 1];
                    *reinterpret_cast<float2*>(&dstrow[cl]) = v;
                }
            }
        }
    }
}

// ---------------------------------------------------------------------------
// TF32 MMA flash attention (R3 structure; Q already tf32, epilogue emits tf32)
// ---------------------------------------------------------------------------
#define AQ_LD 132
#define AV_LD 136
#define AP_LD 68

__global__ __launch_bounds__(256, 1) void attn_mma_kernel(
    const float* __restrict__ Kt,   // [B,nH,T,hd] fp32
    const float* __restrict__ Vt)   // [B,nH,T,hd] fp32
{
    extern __shared__ uint32_t sm[];
    uint32_t* Qs = sm;
    uint32_t* Ks = Qs + 128 * AQ_LD;
    uint32_t* Vs = Ks + 64 * AQ_LD;
    uint32_t* Ps = Vs + 64 * AV_LD;

    const int tid  = threadIdx.x;
    const int lane = tid & 31;
    const int w    = tid >> 5;
    const int iq   = blockIdx.x;
    const int bh   = blockIdx.y;
    const int b    = bh >> 4;
    const int h    = bh & 15;

    const uint32_t* qp = g_qbuf + ((size_t)bh * T_DIM + iq * 128) * HD;
    const float* kp = Kt + (size_t)bh * T_DIM * HD;
    const float* vp = Vt + (size_t)bh * T_DIM * HD;

    // Q tile: already tf32, plain vector copy
#pragma unroll
    for (int r = 0; r < 16; r++) {
        int idx = tid + r * 256;
        int row = idx >> 5;
        int c   = (idx & 31) << 2;
        *reinterpret_cast<uint4*>(&Qs[row * AQ_LD + c]) =
            *reinterpret_cast<const uint4*>(&qp[row * HD + c]);
    }

    const int r0 = lane >> 2;
    float m_i[2] = {-1e30f, -1e30f};
    float l_i[2] = {0.0f, 0.0f};
    float oacc[16][4];
#pragma unroll
    for (int na = 0; na < 16; na++)
#pragma unroll
        for (int c = 0; c < 4; c++) oacc[na][c] = 0.0f;

    const float scale = 0.08838834764831843f;
    const int jmax = 2 * iq + 1;

    for (int j = 0; j <= jmax; j++) {
        __syncthreads();
        const float* kb = kp + (size_t)j * 64 * HD;
        const float* vb = vp + (size_t)j * 64 * HD;
#pragma unroll
        for (int r = 0; r < 8; r++) {
            int idx = tid + r * 256;
            int row = idx >> 5;
            int c   = (idx & 31) << 2;
            float4 kv = *reinterpret_cast<const float4*>(&kb[row * HD + c]);
            Ks[row * AQ_LD + c + 0] = f2tf(kv.x);
            Ks[row * AQ_LD + c + 1] = f2tf(kv.y);
            Ks[row * AQ_LD + c + 2] = f2tf(kv.z);
            Ks[row * AQ_LD + c + 3] = f2tf(kv.w);
            float4 vv = *reinterpret_cast<const float4*>(&vb[row * HD + c]);
            Vs[row * AV_LD + c + 0] = f2tf(vv.x);
            Vs[row * AV_LD + c + 1] = f2tf(vv.y);
            Vs[row * AV_LD + c + 2] = f2tf(vv.z);
            Vs[row * AV_LD + c + 3] = f2tf(vv.w);
        }
        __syncthreads();

        float sacc[8][4];
#pragma unroll
        for (int na = 0; na < 8; na++)
#pragma unroll
            for (int c = 0; c < 4; c++) sacc[na][c] = 0.0f;

#pragma unroll
        for (int ks = 0; ks < 16; ks++) {
            int kc = ks * 8 + (lane & 3);
            uint32_t af[4];
            int mr = w * 16 + r0;
            af[0] = Qs[mr * AQ_LD + kc];
            af[1] = Qs[(mr + 8) * AQ_LD + kc];
            af[2] = Qs[mr * AQ_LD + kc + 4];
            af[3] = Qs[(mr + 8) * AQ_LD + kc + 4];
#pragma unroll
            for (int na = 0; na < 8; na++) {
                uint32_t bf[2];
                int nr = na * 8 + r0;
                bf[0] = Ks[nr * AQ_LD + kc];
                bf[1] = Ks[nr * AQ_LD + kc + 4];
                mma_tf32(sacc[na], af, bf);
            }
        }

#pragma unroll
        for (int na = 0; na < 8; na++)
#pragma unroll
            for (int c = 0; c < 4; c++) sacc[na][c] *= scale;
        if (j >= 2 * iq) {
            int qrow0 = iq * 128 + w * 16 + r0;
#pragma unroll
            for (int na = 0; na < 8; na++) {
                int col = j * 64 + na * 8 + 2 * (lane & 3);
                if (col > qrow0)     sacc[na][0] = -1e30f;
                if (col + 1 > qrow0) sacc[na][1] = -1e30f;
                if (col > qrow0 + 8)     sacc[na][2] = -1e30f;
                if (col + 1 > qrow0 + 8) sacc[na][3] = -1e30f;
            }
        }

        float mt[2] = {-1e30f, -1e30f};
#pragma unroll
        for (int na = 0; na < 8; na++) {
            mt[0] = fmaxf(mt[0], fmaxf(sacc[na][0], sacc[na][1]));
            mt[1] = fmaxf(mt[1], fmaxf(sacc[na][2], sacc[na][3]));
        }
#pragma unroll
        for (int off = 1; off <= 2; off <<= 1) {
            mt[0] = fmaxf(mt[0], __shfl_xor_sync(0xffffffffu, mt[0], off));
            mt[1] = fmaxf(mt[1], __shfl_xor_sync(0xffffffffu, mt[1], off));
        }
        float mnew0 = fmaxf(m_i[0], mt[0]);
        float mnew1 = fmaxf(m_i[1], mt[1]);
        float alpha0 = __expf(m_i[0] - mnew0);
        float alpha1 = __expf(m_i[1] - mnew1);
        m_i[0] = mnew0; m_i[1] = mnew1;

        float sum0 = 0.0f, sum1 = 0.0f;
#pragma unroll
        for (int na = 0; na < 8; na++) {
            float p0 = __expf(sacc[na][0] - mnew0);
            float p1 = __expf(sacc[na][1] - mnew0);
            float p2 = __expf(sacc[na][2] - mnew1);
            float p3 = __expf(sacc[na][3] - mnew1);
            sum0 += p0 + p1; sum1 += p2 + p3;
            int prow = w * 16 + r0;
            int pcol = na * 8 + 2 * (lane & 3);
            uint2 pv0 = make_uint2(f2tf(p0), f2tf(p1));
            uint2 pv1 = make_uint2(f2tf(p2), f2tf(p3));
            *reinterpret_cast<uint2*>(&Ps[prow * AP_LD + pcol]) = pv0;
            *reinterpret_cast<uint2*>(&Ps[(prow + 8) * AP_LD + pcol]) = pv1;
        }
#pragma unroll
        for (int off = 1; off <= 2; off <<= 1) {
            sum0 += __shfl_xor_sync(0xffffffffu, sum0, off);
            sum1 += __shfl_xor_sync(0xffffffffu, sum1, off);
        }
        l_i[0] = l_i[0] * alpha0 + sum0;
        l_i[1] = l_i[1] * alpha1 + sum1;
#pragma unroll
        for (int na = 0; na < 16; na++) {
            oacc[na][0] *= alpha0; oacc[na][1] *= alpha0;
            oacc[na][2] *= alpha1; oacc[na][3] *= alpha1;
        }

        __syncwarp();

#pragma unroll
        for (int ks = 0; ks < 8; ks++) {
            int kc = ks * 8 + (lane & 3);
            uint32_t af[4];
            int mr = w * 16 + r0;
            af[0] = Ps[mr * AP_LD + kc];
            af[1] = Ps[(mr + 8) * AP_LD + kc];
            af[2] = Ps[mr * AP_LD + kc + 4];
            af[3] = Ps[(mr + 8) * AP_LD + kc + 4];
#pragma unroll
            for (int na = 0; na < 16; na++) {
                uint32_t bf[2];
                bf[0] = Vs[kc * AV_LD + na * 8 + r0];
                bf[1] = Vs[(kc + 4) * AV_LD + na * 8 + r0];
                mma_tf32(oacc[na], af, bf);
            }
        }
        __syncwarp();
    }

    // finalize -> g_ybuf (tf32)
    float inv0 = 1.0f / l_i[0];
    float inv1 = 1.0f / l_i[1];
    int t0 = iq * 128 + w * 16 + r0;
    int t1 = t0 + 8;
    uint32_t* dst0 = g_ybuf + ((size_t)(b * T_DIM + t0) * C_DIM) + h * HD;
    uint32_t* dst1 = g_ybuf + ((size_t)(b * T_DIM + t1) * C_DIM) + h * HD;
#pragma unroll
    for (int na = 0; na < 16; na++) {
        int col = na * 8 + 2 * (lane & 3);
        uint2 v0, v1;
        v0.x = f2tf(oacc[na][0] * inv0); v0.y = f2tf(oacc[na][1] * inv0);
        v1.x = f2tf(oacc[na][2] * inv1); v1.y = f2tf(oacc[na][3] * inv1);
        *reinterpret_cast<uint2*>(&dst0[col]) = v0;
        *reinterpret_cast<uint2*>(&dst1[col]) = v1;
    }
}

// ---------------------------------------------------------------------------
extern "C" void kernel_launch(void* const* d_in, const int* in_sizes, int n_in,
                              void* d_out, int out_size)
{
    const float* x    = (const float*)d_in[0];
    const float* Wqkv = (const float*)d_in[1];
    const float* bqkv = (const float*)d_in[2];
    const float* Wout = (const float*)d_in[3];
    const float* bout = (const float*)d_in[4];

    float* y    = (float*)d_out;
    float* kout = y + YELEMS;
    float* vout = y + 2 * YELEMS;

    uint32_t *xtf, *wqkvtf, *wouttf, *ybuf;
    cudaGetSymbolAddress((void**)&xtf,    g_xtf);
    cudaGetSymbolAddress((void**)&wqkvtf, g_wqkvtf);
    cudaGetSymbolAddress((void**)&wouttf, g_wouttf);
    cudaGetSymbolAddress((void**)&ybuf,   g_ybuf);

    const int attn_smem =
        (128 * AQ_LD + 64 * AQ_LD + 64 * AV_LD + 128 * AP_LD) * 4;  // 171008
    cudaFuncSetAttribute(attn_mma_kernel,
                         cudaFuncAttributeMaxDynamicSharedMemorySize, attn_smem);

    // 0) tf32 pre-conversion of GEMM inputs (bandwidth-bound, ~50us)
    cvt_tf32_kernel<<<2048, 256>>>((const float4*)x, (uint4*)xtf, YELEMS / 4);
    cvt_tf32_kernel<<<2048, 256>>>((const float4*)Wqkv, (uint4*)wqkvtf,
                                   3 * C_DIM * C_DIM / 4);
    cvt_tf32_kernel<<<1024, 256>>>((const float4*)Wout, (uint4*)wouttf,
                                   C_DIM * C_DIM / 4);

    // 1) QKV projection (tf32 MMA, cp.async) + head scatter
    mma_gemm<0><<<dim3(3 * C_DIM / BN, MTOT / BM), 256>>>(
        xtf, wqkvtf, bqkv, kout, vout);

    // 2) causal flash attention (tf32 MMA) -> g_ybuf (tf32)
    attn_mma_kernel<<<dim3(T_DIM / 128, B_DIM * NH), 256, attn_smem>>>(
        kout, vout);

    // 3) output projection -> y
    mma_gemm<1><<<dim3(C_DIM / BN, MTOT / BM), 256>>>(
        ybuf, wouttf, bout, y, nullptr);
}